// round 16
// baseline (speedup 1.0000x reference)
#include <cuda_runtime.h>
#include <math.h>
#include <stdint.h>

#define D 128
#define C 10
#define NMAX 4096
#define BT 128
#define GS 132                         // padded fragment-group stride (words)
#define STAGE_W (32 * GS)              // words per matrix per stage (4224)
#define DYN_SMEM (2 * 2 * STAGE_W * 4) // 67584 B
#define NREP 8                         // global accumulator replicas

// -------- device scratch (zero-init; finalize self-resets) --------
__device__ double g_Sacc[NREP][32];
__device__ int    g_counts[C];
__device__ float  g_sq[NMAX];
__device__ float  g_projT[C * NMAX];   // [class][row], coalesced loads
__device__ int    g_cls[NMAX];
__device__ float  g_pcl[NMAX];
__device__ float  g_invwnCls[NMAX];
__device__ unsigned int g_done = 0;

__device__ __forceinline__ int clampC(int v) { return v < 0 ? 0 : (v >= C ? C - 1 : v); }

// rsqrt without MUFU: magic seed + 2 Newton steps (rel err ~4e-6)
__device__ __forceinline__ float fast_rsqrt(float x) {
    float y = __int_as_float(0x5f3759dfu - (__float_as_int(x) >> 1));
    float xh = -0.5f * x;
    y = y * fmaf(xh, y * y, 1.5f);
    y = y * fmaf(xh, y * y, 1.5f);
    return y;
}
__device__ __forceinline__ void mma_tf32(float* d, const uint32_t* a,
                                         uint32_t b0, uint32_t b1) {
    asm volatile(
        "mma.sync.aligned.m16n8k8.row.col.f32.tf32.tf32.f32 "
        "{%0,%1,%2,%3}, {%4,%5,%6,%7}, {%8,%9}, {%0,%1,%2,%3};"
        : "+f"(d[0]), "+f"(d[1]), "+f"(d[2]), "+f"(d[3])
        : "r"(a[0]), "r"(a[1]), "r"(a[2]), "r"(a[3]), "r"(b0), "r"(b1));
}
__device__ __forceinline__ float red2(float v) {    // sum over tig (xor 1,2)
    v += __shfl_xor_sync(0xffffffffu, v, 1);
    v += __shfl_xor_sync(0xffffffffu, v, 2);
    return v;
}
__device__ __forceinline__ float red8(float v) {    // sum over g2 (xor 4,8,16)
    v += __shfl_xor_sync(0xffffffffu, v, 4);
    v += __shfl_xor_sync(0xffffffffu, v, 8);
    v += __shfl_xor_sync(0xffffffffu, v, 16);
    return v;
}

// ---------------- prep: counts + per-row sq, projT, derived scalars ----------
__global__ void prep(const float* __restrict__ pred,
                     const int* __restrict__ target,
                     const float* __restrict__ W, int N)
{
    __shared__ float Wsh[C][D];
    __shared__ float wnInv[C];
    __shared__ int   cnt[C];
    int tid = threadIdx.x;
    if (tid < C) cnt[tid] = 0;
    for (int i = tid; i < C * D; i += blockDim.x) Wsh[i / D][i % D] = W[i];
    __syncthreads();
    if (tid < C) {
        float s = 0.f;
        #pragma unroll 16
        for (int k = 0; k < D; k++) { float w = Wsh[tid][k]; s = fmaf(w, w, s); }
        wnInv[tid] = 1.0f / fmaxf(sqrtf(s), 1e-8f);
    }
    __syncthreads();

    int r = blockIdx.x * blockDim.x + tid;
    if (r < N) {
        int cl = clampC(target[r]);
        atomicAdd(&cnt[cl], 1);

        const float4* p4 = (const float4*)(pred + (size_t)r * D);
        float sq = 0.f;
        float proj[C];
        #pragma unroll
        for (int c = 0; c < C; c++) proj[c] = 0.f;
        #pragma unroll 4
        for (int q = 0; q < D / 4; q++) {
            float4 v = p4[q];
            float vv[4] = {v.x, v.y, v.z, v.w};
            #pragma unroll
            for (int j = 0; j < 4; j++) {
                float p = vv[j];
                int k = q * 4 + j;
                sq = fmaf(p, p, sq);
                #pragma unroll
                for (int c = 0; c < C; c++) proj[c] = fmaf(p, Wsh[c][k], proj[c]);
            }
        }
        g_sq[r]  = sq;
        g_cls[r] = cl;
        #pragma unroll
        for (int c = 0; c < C; c++) g_projT[c * NMAX + r] = proj[c];
        g_pcl[r]      = proj[cl];
        g_invwnCls[r] = wnInv[cl];
    }
    __syncthreads();
    if (tid < C && cnt[tid] > 0) atomicAdd(&g_counts[tid], cnt[tid]);
}

// ---- main: raw-bits tf32 HMMA + two-pass low-pressure epilogue --------------
__global__ __launch_bounds__(256, 2)
void pairKernel(const float* __restrict__ pred, float* __restrict__ out, int nb)
{
    extern __shared__ uint32_t dyn[];   // [stage][A STAGE_W | B STAGE_W]
    __shared__ float projA[C][132];
    __shared__ float projB[C][132];
    __shared__ float aSq[BT], aP[BT], aIW[BT], aIC[BT];
    __shared__ float bSq[BT], bP[BT], bIW[BT], bIC[BT];
    __shared__ int   aCl[BT], bCl[BT];
    __shared__ float rA0[BT], rA1[BT], rA2[BT];
    __shared__ float tB0[BT], tB1[BT], tB2[BT];
    __shared__ float icT[16];
    __shared__ float sacc[32];          // f32 per-CTA class accumulators

    int tid  = threadIdx.x;
    int lane = tid & 31, wid = tid >> 5;
    int wm = wid >> 2, wn = wid & 3;      // warp grid 2(m) x 4(n)
    int g2 = lane >> 2, tig = lane & 3;

    int idx = blockIdx.x;
    int bi = (int)(((float)(2 * nb + 1)
             - sqrtf((float)((2 * nb + 1) * (2 * nb + 1) - 8 * idx))) * 0.5f);
    while ((bi + 1) * nb - ((bi + 1) * bi) / 2 <= idx) bi++;
    while (bi * nb - (bi * (bi - 1)) / 2 > idx) bi--;
    int bj = bi + (idx - (bi * nb - (bi * (bi - 1)) / 2));
    int aBase = bi * BT, bBase = bj * BT;
    bool offd = (bi != bj);

    // ---- meta fill ----
    if (tid < 32) sacc[tid] = 0.f;
    if (tid < C)  icT[tid] = 1.0f / (float)max(g_counts[tid], 1);
    if (tid < BT) {
        int ga = aBase + tid, gb = bBase + tid;
        aSq[tid] = g_sq[ga]; aP[tid] = g_pcl[ga]; aIW[tid] = g_invwnCls[ga];
        aCl[tid] = g_cls[ga];
        bSq[tid] = g_sq[gb]; bP[tid] = g_pcl[gb]; bIW[tid] = g_invwnCls[gb];
        bCl[tid] = g_cls[gb];
        rA0[tid] = 0.f; rA1[tid] = 0.f; rA2[tid] = 0.f;
        tB0[tid] = 0.f; tB1[tid] = 0.f; tB2[tid] = 0.f;
    }
    for (int i = tid; i < C * BT; i += 256) {
        int c = i >> 7, b = i & 127;
        projB[c][b] = g_projT[c * NMAX + bBase + b];
        if (offd) projA[c][b] = g_projT[c * NMAX + aBase + b];
    }
    __syncthreads();
    if (tid < BT) {
        aIC[tid] = icT[aCl[tid]];
        bIC[tid] = icT[bCl[tid]];
    }

    // ---- fill-index precompute ----
    int gofs[4], aofs[4], bofs[4];
    #pragma unroll
    for (int i = 0; i < 4; i++) {
        int ix = i * 256 + tid;
        int r = ix >> 3, c = ix & 7;          // c = float4 column (0..7)
        gofs[i] = r * D + c * 4;
        aofs[i] = ((r >> 4) * 4 + (c >> 1)) * GS + (r & 7) * 16
                + ((r >> 3) & 1) + ((c & 1) << 1);
        bofs[i] = ((r >> 4) * 4 + (c >> 1)) * GS + (r & 7) * 16
                + (((r >> 3) & 1) << 1) + (c & 1);
    }
    const float* gA = pred + (size_t)aBase * D;
    const float* gB = pred + (size_t)bBase * D;

    float dacc[4][4][4];
    #pragma unroll
    for (int a = 0; a < 4; a++)
        #pragma unroll
        for (int b = 0; b < 4; b++)
            #pragma unroll
            for (int e = 0; e < 4; e++) dacc[a][b][e] = 0.f;

    // prefetch chunk 0 (raw bits: no tf32 conversion — HMMA truncates)
    uint4 fa[4], fb[4];
    #pragma unroll
    for (int i = 0; i < 4; i++) {
        fa[i] = *(const uint4*)(gA + gofs[i]);
        fb[i] = *(const uint4*)(gB + gofs[i]);
    }

    #pragma unroll
    for (int ch = 0; ch < 4; ch++) {
        uint32_t* dA = dyn + (ch & 1) * (2 * STAGE_W);
        uint32_t* dB = dA + STAGE_W;
        #pragma unroll
        for (int i = 0; i < 4; i++) {
            dA[aofs[i] + 0]  = fa[i].x;
            dA[aofs[i] + 4]  = fa[i].y;
            dA[aofs[i] + 8]  = fa[i].z;
            dA[aofs[i] + 12] = fa[i].w;
            dB[bofs[i] + 0]  = fb[i].x;
            dB[bofs[i] + 4]  = fb[i].y;
            dB[bofs[i] + 8]  = fb[i].z;
            dB[bofs[i] + 12] = fb[i].w;
        }
        if (ch < 3) {
            int kb = (ch + 1) * 32;
            #pragma unroll
            for (int i = 0; i < 4; i++) {
                fa[i] = *(const uint4*)(gA + kb + gofs[i]);
                fb[i] = *(const uint4*)(gB + kb + gofs[i]);
            }
        }
        __syncthreads();
        #pragma unroll
        for (int k8 = 0; k8 < 4; k8++) {
            uint4 bq0 = *(const uint4*)(dB + ((wn * 2 + 0) * 4 + k8) * GS + lane * 4);
            uint4 bq1 = *(const uint4*)(dB + ((wn * 2 + 1) * 4 + k8) * GS + lane * 4);
            #pragma unroll
            for (int fm = 0; fm < 4; fm++) {
                uint4 aq = *(const uint4*)(dA + ((wm * 4 + fm) * 4 + k8) * GS + lane * 4);
                uint32_t A4[4] = {aq.x, aq.y, aq.z, aq.w};
                mma_tf32(dacc[fm][0], A4, bq0.x, bq0.y);
                mma_tf32(dacc[fm][1], A4, bq0.z, bq0.w);
                mma_tf32(dacc[fm][2], A4, bq1.x, bq1.y);
                mma_tf32(dacc[fm][3], A4, bq1.z, bq1.w);
            }
        }
    }

    // -------- epilogue pass A: row sums (low register pressure) --------
    #pragma unroll
    for (int fm = 0; fm < 4; fm++) {
        #pragma unroll
        for (int rr = 0; rr < 2; rr++) {
            int r = wm * 64 + fm * 16 + g2 + rr * 8;          // tig-independent
            int   ca  = aCl[r];
            float pa  = aP[r], iw = aIW[r], ica = aIC[r], sqa = aSq[r];
            const float* pjr = projB[ca];
            float s0 = 0.f, s1 = 0.f, s2 = 0.f;
            #pragma unroll
            for (int j = 0; j < 8; j++) {
                int c = wn * 32 + (j >> 1) * 8 + 2 * tig + (j & 1);
                float gv = dacc[fm][j >> 1][rr * 2 + (j & 1)];
                float d2 = fmaxf(sqa + bSq[c] - 2.0f * gv, 0.0f) + 1e-16f;
                float invdn = fast_rsqrt(d2);
                if (bCl[c] != ca) {
                    float w = ica * bIC[c];
                    float MA = (pa - pjr[c]) * iw * invdn;
                    s0 += w; s1 = fmaf(w, MA, s1); s2 = fmaf(w * MA, MA, s2);
                }
            }
            s0 = red2(s0); s1 = red2(s1); s2 = red2(s2);      // 4 lanes share r
            if (tig == 0) {
                atomicAdd(&rA0[r], s0); atomicAdd(&rA1[r], s1); atomicAdd(&rA2[r], s2);
            }
        }
    }

    // -------- epilogue pass B (off-diag): col sums, invdn recomputed --------
    if (offd) {
        #pragma unroll
        for (int j = 0; j < 8; j++) {
            int c = wn * 32 + (j >> 1) * 8 + 2 * tig + (j & 1);   // g2-independent
            int   ccl = bCl[c];
            float cpv = bP[c], ciw = bIW[c], cic = bIC[c], csq = bSq[c];
            const float* pjc = projA[ccl];
            float u0 = 0.f, u1 = 0.f, u2 = 0.f;
            #pragma unroll
            for (int fm = 0; fm < 4; fm++) {
                #pragma unroll
                for (int rr = 0; rr < 2; rr++) {
                    int r = wm * 64 + fm * 16 + g2 + rr * 8;
                    float gv = dacc[fm][j >> 1][rr * 2 + (j & 1)];
                    float d2 = fmaxf(aSq[r] + csq - 2.0f * gv, 0.0f) + 1e-16f;
                    float invdn = fast_rsqrt(d2);
                    if (ccl != aCl[r]) {
                        float w = aIC[r] * cic;
                        float MB = (cpv - pjc[r]) * ciw * invdn;
                        u0 += w; u1 = fmaf(w, MB, u1); u2 = fmaf(w * MB, MB, u2);
                    }
                }
            }
            u0 = red8(u0); u1 = red8(u1); u2 = red8(u2);      // 8 lanes share c
            if (g2 == 0) {
                atomicAdd(&tB0[c], u0); atomicAdd(&tB1[c], u1); atomicAdd(&tB2[c], u2);
            }
        }
    }
    __syncthreads();

    if (tid < BT) {
        int ca = aCl[tid];
        atomicAdd(&sacc[ca * 3 + 0], rA0[tid]);
        atomicAdd(&sacc[ca * 3 + 1], rA1[tid]);
        atomicAdd(&sacc[ca * 3 + 2], rA2[tid]);
    } else if (offd) {
        int c = tid - BT;
        int cb = bCl[c];
        atomicAdd(&sacc[cb * 3 + 0], tB0[c]);
        atomicAdd(&sacc[cb * 3 + 1], tB1[c]);
        atomicAdd(&sacc[cb * 3 + 2], tB2[c]);
    }
    __syncthreads();
    // replicated global accumulators: per-address serialization / NREP
    int rep = blockIdx.x & (NREP - 1);
    if (tid < 30) atomicAdd(&g_Sacc[rep][tid], (double)sacc[tid]);

    // -------- fused finalize (warp-parallel in the last CTA) --------
    __threadfence();
    __syncthreads();
    if (wid == 0) {
        unsigned int old = 0;
        if (lane == 0) old = atomicAdd(&g_done, 1u);
        old = __shfl_sync(0xffffffffu, old, 0);
        if (old == gridDim.x - 1) {
            __threadfence();
            double l1c = 0.0, l2c = 0.0;
            int e = 0;
            #pragma unroll
            for (int c = 0; c < C; c++) e += (g_counts[c] > 0);
            double ed  = (double)e;
            double inv = 1.0 / (ed - 1.0);
            if (lane < C && g_counts[lane] > 0) {
                double S0 = 0.0, S1 = 0.0, S2 = 0.0;
                #pragma unroll
                for (int rp = 0; rp < NREP; rp++) {
                    S0 += g_Sacc[rp][lane * 3 + 0];
                    S1 += g_Sacc[rp][lane * 3 + 1];
                    S2 += g_Sacc[rp][lane * 3 + 2];
                }
                l1c = (S0 - 2.0 * S1 + S2) * inv;
                double mm = S1 * inv;
                double mv = (S2 - 2.0 * mm * S1 + mm * mm * S0) * inv;
                l2c = fabs(mv / mm);
            }
            #pragma unroll
            for (int off = 16; off > 0; off >>= 1) {
                l1c += __shfl_down_sync(0xffffffffu, l1c, off);
                l2c += __shfl_down_sync(0xffffffffu, l2c, off);
            }
            if (lane == 0) {
                out[0] = (float)(l1c / ed);
                out[1] = (float)(l2c / ed);
            }
            for (int i = lane; i < NREP * 32; i += 32)
                g_Sacc[i >> 5][i & 31] = 0.0;
            if (lane < C) g_counts[lane] = 0;
            __threadfence();
            if (lane == 0) g_done = 0;
        }
    }
}

// ---------------- launch ----------------
extern "C" void kernel_launch(void* const* d_in, const int* in_sizes, int n_in,
                              void* d_out, int out_size)
{
    const float* pred   = (const float*)d_in[0];
    const int*   target = (const int*)d_in[1];   // JAX x64-disabled: int64 -> int32
    const float* W      = (const float*)d_in[2];
    int N = in_sizes[0] / D;                     // 4096
    int nb = N / BT;                             // 32
    int nblk = nb * (nb + 1) / 2;                // 528

    cudaFuncSetAttribute(pairKernel, cudaFuncAttributeMaxDynamicSharedMemorySize, DYN_SMEM);

    prep<<<(N + 127) / 128, 128>>>(pred, target, W, N);
    pairKernel<<<nblk, 256, DYN_SMEM>>>(pred, (float*)d_out, nb);
}

// round 17
// speedup vs baseline: 1.0882x; 1.0882x over previous
#include <cuda_runtime.h>
#include <math.h>
#include <stdint.h>

#define D 128
#define C 10
#define NMAX 4096
#define BT 128
#define GS 132                         // padded fragment-group stride (words)
#define STAGE_W (32 * GS)              // words per matrix per stage (4224)
#define DYN_SMEM (2 * 2 * STAGE_W * 4) // 67584 B
#define NREP 8                         // global accumulator replicas
#define NTILE 528
#define GRID 264                       // 2 tiles per CTA, single wave (<296)

// -------- device scratch (zero-init; finalize self-resets) --------
__device__ double g_Sacc[NREP][32];
__device__ int    g_counts[C];
__device__ float  g_sq[NMAX];
__device__ float  g_projT[C * NMAX];   // [class][row], coalesced loads
__device__ int    g_cls[NMAX];
__device__ float  g_pcl[NMAX];
__device__ float  g_invwnCls[NMAX];
__device__ unsigned int g_done = 0;

__device__ __forceinline__ int clampC(int v) { return v < 0 ? 0 : (v >= C ? C - 1 : v); }

// rsqrt without MUFU: magic seed + 2 Newton steps (rel err ~4e-6)
__device__ __forceinline__ float fast_rsqrt(float x) {
    float y = __int_as_float(0x5f3759dfu - (__float_as_int(x) >> 1));
    float xh = -0.5f * x;
    y = y * fmaf(xh, y * y, 1.5f);
    y = y * fmaf(xh, y * y, 1.5f);
    return y;
}
__device__ __forceinline__ void mma_tf32(float* d, const uint32_t* a,
                                         uint32_t b0, uint32_t b1) {
    asm volatile(
        "mma.sync.aligned.m16n8k8.row.col.f32.tf32.tf32.f32 "
        "{%0,%1,%2,%3}, {%4,%5,%6,%7}, {%8,%9}, {%0,%1,%2,%3};"
        : "+f"(d[0]), "+f"(d[1]), "+f"(d[2]), "+f"(d[3])
        : "r"(a[0]), "r"(a[1]), "r"(a[2]), "r"(a[3]), "r"(b0), "r"(b1));
}
__device__ __forceinline__ uint32_t cvt_tf32(float v) {
    uint32_t u; asm("cvt.rna.tf32.f32 %0, %1;" : "=r"(u) : "f"(v)); return u;
}
__device__ __forceinline__ float red2(float v) {    // sum over tig (xor 1,2)
    v += __shfl_xor_sync(0xffffffffu, v, 1);
    v += __shfl_xor_sync(0xffffffffu, v, 2);
    return v;
}
__device__ __forceinline__ float red8(float v) {    // sum over g2 (xor 4,8,16)
    v += __shfl_xor_sync(0xffffffffu, v, 4);
    v += __shfl_xor_sync(0xffffffffu, v, 8);
    v += __shfl_xor_sync(0xffffffffu, v, 16);
    return v;
}

// ---------------- prep: counts + per-row sq, projT, derived scalars ----------
__global__ void prep(const float* __restrict__ pred,
                     const int* __restrict__ target,
                     const float* __restrict__ W, int N)
{
    __shared__ float Wsh[C][D];
    __shared__ float wnInv[C];
    __shared__ int   cnt[C];
    int tid = threadIdx.x;
    if (tid < C) cnt[tid] = 0;
    for (int i = tid; i < C * D; i += blockDim.x) Wsh[i / D][i % D] = W[i];
    __syncthreads();
    if (tid < C) {
        float s = 0.f;
        #pragma unroll 16
        for (int k = 0; k < D; k++) { float w = Wsh[tid][k]; s = fmaf(w, w, s); }
        wnInv[tid] = 1.0f / fmaxf(sqrtf(s), 1e-8f);
    }
    __syncthreads();

    int r = blockIdx.x * blockDim.x + tid;
    if (r < N) {
        int cl = clampC(target[r]);
        atomicAdd(&cnt[cl], 1);

        const float4* p4 = (const float4*)(pred + (size_t)r * D);
        float sq = 0.f;
        float proj[C];
        #pragma unroll
        for (int c = 0; c < C; c++) proj[c] = 0.f;
        #pragma unroll 4
        for (int q = 0; q < D / 4; q++) {
            float4 v = p4[q];
            float vv[4] = {v.x, v.y, v.z, v.w};
            #pragma unroll
            for (int j = 0; j < 4; j++) {
                float p = vv[j];
                int k = q * 4 + j;
                sq = fmaf(p, p, sq);
                #pragma unroll
                for (int c = 0; c < C; c++) proj[c] = fmaf(p, Wsh[c][k], proj[c]);
            }
        }
        g_sq[r]  = sq;
        g_cls[r] = cl;
        #pragma unroll
        for (int c = 0; c < C; c++) g_projT[c * NMAX + r] = proj[c];
        g_pcl[r]      = proj[cl];
        g_invwnCls[r] = wnInv[cl];
    }
    __syncthreads();
    if (tid < C && cnt[tid] > 0) atomicAdd(&g_counts[tid], cnt[tid]);
}

// ---- main: R15 per-tile body, 2 tiles per CTA (single wave), 1 flush --------
__global__ __launch_bounds__(256, 2)
void pairKernel(const float* __restrict__ pred, float* __restrict__ out, int nb)
{
    extern __shared__ uint32_t dyn[];   // [stage][A STAGE_W | B STAGE_W]
    __shared__ float projA[C][132];
    __shared__ float projB[C][132];
    __shared__ float aSq[BT], aP[BT], aIW[BT], aIC[BT];
    __shared__ float bSq[BT], bP[BT], bIW[BT], bIC[BT];
    __shared__ int   aCl[BT], bCl[BT];
    __shared__ float rA0[BT], rA1[BT], rA2[BT];
    __shared__ float tB0[BT], tB1[BT], tB2[BT];
    __shared__ float icT[16];
    __shared__ float sacc[32];          // f32 per-CTA class accumulators (both tiles)

    int tid  = threadIdx.x;
    int lane = tid & 31, wid = tid >> 5;
    int wm = wid >> 2, wn = wid & 3;      // warp grid 2(m) x 4(n)
    int g2 = lane >> 2, tig = lane & 3;

    if (tid < 32) sacc[tid] = 0.f;
    if (tid < C)  icT[tid] = 1.0f / (float)max(g_counts[tid], 1);

    // ---- fill-index precompute (tile-independent) ----
    int gofs[4], aofs[4], bofs[4];
    #pragma unroll
    for (int i = 0; i < 4; i++) {
        int ix = i * 256 + tid;
        int r = ix >> 3, c = ix & 7;          // c = float4 column (0..7)
        gofs[i] = r * D + c * 4;
        aofs[i] = ((r >> 4) * 4 + (c >> 1)) * GS + (r & 7) * 16
                + ((r >> 3) & 1) + ((c & 1) << 1);
        bofs[i] = ((r >> 4) * 4 + (c >> 1)) * GS + (r & 7) * 16
                + (((r >> 3) & 1) << 1) + (c & 1);
    }

    for (int idx = blockIdx.x; idx < NTILE; idx += GRID) {
        int bi = (int)(((float)(2 * nb + 1)
                 - sqrtf((float)((2 * nb + 1) * (2 * nb + 1) - 8 * idx))) * 0.5f);
        while ((bi + 1) * nb - ((bi + 1) * bi) / 2 <= idx) bi++;
        while (bi * nb - (bi * (bi - 1)) / 2 > idx) bi--;
        int bj = bi + (idx - (bi * nb - (bi * (bi - 1)) / 2));
        int aBase = bi * BT, bBase = bj * BT;
        bool offd = (bi != bj);

        // ---- meta fill (rA/tB re-zeroed per tile) ----
        if (tid < BT) {
            int ga = aBase + tid, gb = bBase + tid;
            aSq[tid] = g_sq[ga]; aP[tid] = g_pcl[ga]; aIW[tid] = g_invwnCls[ga];
            aCl[tid] = g_cls[ga];
            bSq[tid] = g_sq[gb]; bP[tid] = g_pcl[gb]; bIW[tid] = g_invwnCls[gb];
            bCl[tid] = g_cls[gb];
            rA0[tid] = 0.f; rA1[tid] = 0.f; rA2[tid] = 0.f;
            tB0[tid] = 0.f; tB1[tid] = 0.f; tB2[tid] = 0.f;
        }
        for (int i = tid; i < C * BT; i += 256) {
            int c = i >> 7, b = i & 127;
            projB[c][b] = g_projT[c * NMAX + bBase + b];
            if (offd) projA[c][b] = g_projT[c * NMAX + aBase + b];
        }
        __syncthreads();
        if (tid < BT) {
            aIC[tid] = icT[aCl[tid]];
            bIC[tid] = icT[bCl[tid]];
        }

        const float* gA = pred + (size_t)aBase * D;
        const float* gB = pred + (size_t)bBase * D;

        float dacc[4][4][4];
        #pragma unroll
        for (int a = 0; a < 4; a++)
            #pragma unroll
            for (int b = 0; b < 4; b++)
                #pragma unroll
                for (int e = 0; e < 4; e++) dacc[a][b][e] = 0.f;

        // prefetch chunk 0
        float4 fa[4], fb[4];
        #pragma unroll
        for (int i = 0; i < 4; i++) {
            fa[i] = *(const float4*)(gA + gofs[i]);
            fb[i] = *(const float4*)(gB + gofs[i]);
        }

        #pragma unroll
        for (int ch = 0; ch < 4; ch++) {
            uint32_t* dA = dyn + (ch & 1) * (2 * STAGE_W);
            uint32_t* dB = dA + STAGE_W;
            #pragma unroll
            for (int i = 0; i < 4; i++) {
                dA[aofs[i] + 0]  = cvt_tf32(fa[i].x);
                dA[aofs[i] + 4]  = cvt_tf32(fa[i].y);
                dA[aofs[i] + 8]  = cvt_tf32(fa[i].z);
                dA[aofs[i] + 12] = cvt_tf32(fa[i].w);
                dB[bofs[i] + 0]  = cvt_tf32(fb[i].x);
                dB[bofs[i] + 4]  = cvt_tf32(fb[i].y);
                dB[bofs[i] + 8]  = cvt_tf32(fb[i].z);
                dB[bofs[i] + 12] = cvt_tf32(fb[i].w);
            }
            if (ch < 3) {
                int kb = (ch + 1) * 32;
                #pragma unroll
                for (int i = 0; i < 4; i++) {
                    fa[i] = *(const float4*)(gA + kb + gofs[i]);
                    fb[i] = *(const float4*)(gB + kb + gofs[i]);
                }
            }
            __syncthreads();
            #pragma unroll
            for (int k8 = 0; k8 < 4; k8++) {
                uint4 bq0 = *(const uint4*)(dB + ((wn * 2 + 0) * 4 + k8) * GS + lane * 4);
                uint4 bq1 = *(const uint4*)(dB + ((wn * 2 + 1) * 4 + k8) * GS + lane * 4);
                #pragma unroll
                for (int fm = 0; fm < 4; fm++) {
                    uint4 aq = *(const uint4*)(dA + ((wm * 4 + fm) * 4 + k8) * GS + lane * 4);
                    uint32_t A4[4] = {aq.x, aq.y, aq.z, aq.w};
                    mma_tf32(dacc[fm][0], A4, bq0.x, bq0.y);
                    mma_tf32(dacc[fm][1], A4, bq0.z, bq0.w);
                    mma_tf32(dacc[fm][2], A4, bq1.x, bq1.y);
                    mma_tf32(dacc[fm][3], A4, bq1.z, bq1.w);
                }
            }
        }

        // -------- epilogue: per-pair loss; shuffle pre-reduction --------
        int   cV[8], cCl[8];
        float cSq[8], cIC[8];
        #pragma unroll
        for (int j = 0; j < 8; j++) {
            int c = wn * 32 + (j >> 1) * 8 + 2 * tig + (j & 1);   // g2-independent
            cV[j] = c; cSq[j] = bSq[c]; cIC[j] = bIC[c]; cCl[j] = bCl[c];
        }
        float cP[8], cIW[8];
        if (offd) {
            #pragma unroll
            for (int j = 0; j < 8; j++) { cP[j] = bP[cV[j]]; cIW[j] = bIW[cV[j]]; }
        }

        float t0[8], t1[8], t2[8];
        #pragma unroll
        for (int j = 0; j < 8; j++) { t0[j] = 0.f; t1[j] = 0.f; t2[j] = 0.f; }

        #pragma unroll
        for (int fm = 0; fm < 4; fm++) {
            #pragma unroll
            for (int rr = 0; rr < 2; rr++) {
                int r = wm * 64 + fm * 16 + g2 + rr * 8;          // tig-independent
                int   ca  = aCl[r];
                float pa  = aP[r], iw = aIW[r], ica = aIC[r], sqa = aSq[r];
                const float* pjr = projB[ca];
                float s0 = 0.f, s1 = 0.f, s2 = 0.f;
                #pragma unroll
                for (int j = 0; j < 8; j++) {
                    float gv = dacc[fm][j >> 1][rr * 2 + (j & 1)];
                    float d2 = fmaxf(sqa + cSq[j] - 2.0f * gv, 0.0f) + 1e-16f;
                    float invdn = fast_rsqrt(d2);
                    int cb = cCl[j];
                    if (cb != ca) {
                        float w = ica * cIC[j];
                        float MA = (pa - pjr[cV[j]]) * iw * invdn;
                        s0 += w; s1 = fmaf(w, MA, s1); s2 = fmaf(w * MA, MA, s2);
                        if (offd) {
                            float MB = (cP[j] - projA[cb][r]) * cIW[j] * invdn;
                            t0[j] += w; t1[j] = fmaf(w, MB, t1[j]); t2[j] = fmaf(w * MB, MB, t2[j]);
                        }
                    }
                }
                s0 = red2(s0); s1 = red2(s1); s2 = red2(s2);      // 4 lanes share r
                if (tig == 0) {
                    atomicAdd(&rA0[r], s0); atomicAdd(&rA1[r], s1); atomicAdd(&rA2[r], s2);
                }
            }
        }
        if (offd) {
            #pragma unroll
            for (int j = 0; j < 8; j++) {
                float u0 = red8(t0[j]), u1 = red8(t1[j]), u2 = red8(t2[j]);  // 8 share c
                if (g2 == 0) {
                    atomicAdd(&tB0[cV[j]], u0);
                    atomicAdd(&tB1[cV[j]], u1);
                    atomicAdd(&tB2[cV[j]], u2);
                }
            }
        }
        __syncthreads();

        if (tid < BT) {
            int ca = aCl[tid];
            atomicAdd(&sacc[ca * 3 + 0], rA0[tid]);
            atomicAdd(&sacc[ca * 3 + 1], rA1[tid]);
            atomicAdd(&sacc[ca * 3 + 2], rA2[tid]);
        } else if (offd) {
            int c = tid - BT;
            int cb = bCl[c];
            atomicAdd(&sacc[cb * 3 + 0], tB0[c]);
            atomicAdd(&sacc[cb * 3 + 1], tB1[c]);
            atomicAdd(&sacc[cb * 3 + 2], tB2[c]);
        }
        __syncthreads();   // sacc settled; rA/tB free for next tile's meta fill
    }

    // replicated global accumulators: ONE flush per CTA (both tiles)
    int rep = blockIdx.x & (NREP - 1);
    if (tid < 30) atomicAdd(&g_Sacc[rep][tid], (double)sacc[tid]);

    // -------- fused finalize (warp-parallel in the last CTA) --------
    __threadfence();
    __syncthreads();
    if (wid == 0) {
        unsigned int old = 0;
        if (lane == 0) old = atomicAdd(&g_done, 1u);
        old = __shfl_sync(0xffffffffu, old, 0);
        if (old == gridDim.x - 1) {
            __threadfence();
            double l1c = 0.0, l2c = 0.0;
            int e = 0;
            #pragma unroll
            for (int c = 0; c < C; c++) e += (g_counts[c] > 0);
            double ed  = (double)e;
            double inv = 1.0 / (ed - 1.0);
            if (lane < C && g_counts[lane] > 0) {
                double S0 = 0.0, S1 = 0.0, S2 = 0.0;
                #pragma unroll
                for (int rp = 0; rp < NREP; rp++) {
                    S0 += g_Sacc[rp][lane * 3 + 0];
                    S1 += g_Sacc[rp][lane * 3 + 1];
                    S2 += g_Sacc[rp][lane * 3 + 2];
                }
                l1c = (S0 - 2.0 * S1 + S2) * inv;
                double mm = S1 * inv;
                double mv = (S2 - 2.0 * mm * S1 + mm * mm * S0) * inv;
                l2c = fabs(mv / mm);
            }
            #pragma unroll
            for (int off = 16; off > 0; off >>= 1) {
                l1c += __shfl_down_sync(0xffffffffu, l1c, off);
                l2c += __shfl_down_sync(0xffffffffu, l2c, off);
            }
            if (lane == 0) {
                out[0] = (float)(l1c / ed);
                out[1] = (float)(l2c / ed);
            }
            for (int i = lane; i < NREP * 32; i += 32)
                g_Sacc[i >> 5][i & 31] = 0.0;
            if (lane < C) g_counts[lane] = 0;
            __threadfence();
            if (lane == 0) g_done = 0;
        }
    }
}

// ---------------- launch ----------------
extern "C" void kernel_launch(void* const* d_in, const int* in_sizes, int n_in,
                              void* d_out, int out_size)
{
    const float* pred   = (const float*)d_in[0];
    const int*   target = (const int*)d_in[1];   // JAX x64-disabled: int64 -> int32
    const float* W      = (const float*)d_in[2];
    int N = in_sizes[0] / D;                     // 4096
    int nb = N / BT;                             // 32

    cudaFuncSetAttribute(pairKernel, cudaFuncAttributeMaxDynamicSharedMemorySize, DYN_SMEM);

    prep<<<(N + 127) / 128, 128>>>(pred, target, W, N);
    pairKernel<<<GRID, 256, DYN_SMEM>>>(pred, (float*)d_out, nb);
}